// round 7
// baseline (speedup 1.0000x reference)
#include <cuda_runtime.h>
#include <cstdint>
#include <math.h>

#define SEQ   512
#define BATCH 256
#define INS   58
#define HID   256
#define G3    768
#define NCAT  18

#define SCAN_BLOCKS 128
#define BT 32      // batch tile per block
#define HS 16      // hidden strip per block (gates = 3*HS = 48 rows of W_hh)
#define WPAD 260   // padded row stride for smem tiles (floats, /4 aligned)

// ---------------- device scratch (static allocation only) ----------------
__device__ float g_gx[(size_t)SEQ * BATCH * G3];     // reused per layer
__device__ float g_h0out[(size_t)SEQ * BATCH * HID]; // layer-0 outputs
__device__ float g_hA[BATCH * HID];
__device__ float g_hB[BATCH * HID];
__device__ unsigned g_bar_count = 0;
__device__ unsigned g_bar_gen = 0;

// ---------------- fast gate math -----------------------------------------
__device__ __forceinline__ float fast_sigmoid(float x) {
    return 1.0f / (1.0f + __expf(-x));
}
__device__ __forceinline__ float fast_tanh(float x) {
    // tanh(x) = 1 - 2/(exp(2x)+1); __expf accurate to ~2 ulp
    return 1.0f - 2.0f / (__expf(2.0f * x) + 1.0f);
}

// ---------------- software grid barrier (all blocks co-resident) ---------
__device__ __forceinline__ void grid_barrier(unsigned nb) {
    __syncthreads();
    if (threadIdx.x == 0) {
        __threadfence();                       // release: publish this block's writes
        volatile unsigned* genp = &g_bar_gen;
        unsigned gen = *genp;
        unsigned arrived = atomicAdd(&g_bar_count, 1u);
        if (arrived == nb - 1u) {
            g_bar_count = 0u;
            __threadfence();
            *genp = gen + 1u;
        } else {
            while (*genp == gen) { }
        }
        __threadfence();                       // acquire: see peer blocks' writes
    }
    __syncthreads();
}

// ---------------- generic GEMM: C[M,N] = A[M,K] @ W[N,K]^T + bias[N] -----
__global__ __launch_bounds__(256) void gemm_bias_kernel(
    const float* __restrict__ A, const float* __restrict__ W,
    const float* __restrict__ bias, float* __restrict__ C,
    int M, int N, int K)
{
    __shared__ float As[16][64];
    __shared__ float Bs[16][64];
    const int tid = threadIdx.x;
    const int tx = tid & 15, ty = tid >> 4;
    const int m0 = blockIdx.y * 64, n0 = blockIdx.x * 64;
    const int l_mn = tid >> 2;          // 0..63
    const int l_k0 = (tid & 3) * 4;     // 0,4,8,12

    float acc[4][4];
#pragma unroll
    for (int i = 0; i < 4; i++)
#pragma unroll
        for (int j = 0; j < 4; j++) acc[i][j] = 0.f;

    for (int kk = 0; kk < K; kk += 16) {
#pragma unroll
        for (int i = 0; i < 4; i++) {
            int k = l_k0 + i;
            int gm = m0 + l_mn, gk = kk + k;
            float v = 0.f;
            if (gm < M && gk < K) v = A[(size_t)gm * K + gk];
            As[k][l_mn] = v;
        }
#pragma unroll
        for (int i = 0; i < 4; i++) {
            int k = l_k0 + i;
            int gn = n0 + l_mn, gk = kk + k;
            float v = 0.f;
            if (gn < N && gk < K) v = W[(size_t)gn * K + gk];
            Bs[k][l_mn] = v;
        }
        __syncthreads();
#pragma unroll
        for (int k = 0; k < 16; k++) {
            float4 a = *(const float4*)&As[k][ty * 4];
            float4 b = *(const float4*)&Bs[k][tx * 4];
            float av[4] = {a.x, a.y, a.z, a.w};
            float bv[4] = {b.x, b.y, b.z, b.w};
#pragma unroll
            for (int i = 0; i < 4; i++)
#pragma unroll
                for (int j = 0; j < 4; j++)
                    acc[i][j] = fmaf(av[i], bv[j], acc[i][j]);
        }
        __syncthreads();
    }
#pragma unroll
    for (int i = 0; i < 4; i++) {
        int gm = m0 + ty * 4 + i;
        if (gm >= M) continue;
#pragma unroll
        for (int j = 0; j < 4; j++) {
            int gn = n0 + tx * 4 + j;
            if (gn < N) C[(size_t)gm * N + gn] = acc[i][j] + bias[gn];
        }
    }
}

// ---------------- zero the initial hidden state --------------------------
__global__ void zero_h_kernel() {
    g_hA[blockIdx.x * 256 + threadIdx.x] = 0.f;
}

// ---------------- persistent GRU scan over T ------------------------------
// grid = 128 blocks (8 batch tiles x 16 hidden strips), 256 threads.
// Each block: gh = h(32x256) @ W_strip(48x256)^T, gate math, h-update for
// its (32 x 16) h tile. Ping/pong h buffers in gmem, 1 grid barrier/step.
template <bool STORE_ALL>
__global__ __launch_bounds__(256) void gru_scan_kernel(
    const float* __restrict__ W_hh, const float* __restrict__ b_hh,
    const float* __restrict__ gx, float* __restrict__ h_all)
{
    extern __shared__ float sm[];
    float* Ws  = sm;                       // 48 * WPAD
    float* hs  = Ws + 48 * WPAD;           // BT * WPAD
    float* Gs  = hs + BT * WPAD;           // BT * 52
    float* bsm = Gs + BT * 52;             // 48

    const int tid = threadIdx.x;
    const int bt = blockIdx.x >> 4;        // 0..7   (batch tile)
    const int s  = blockIdx.x & 15;        // 0..15  (hidden strip)

    // load persistent W_hh strip: local row lr -> global row (lr/16)*256 + s*16 + lr%16
    for (int i = tid; i < 48 * (HID / 4); i += 256) {
        int lr = i >> 6;
        int c4 = (i & 63) * 4;
        int grow = (lr >> 4) * HID + s * HS + (lr & 15);
        *(float4*)&Ws[lr * WPAD + c4] = *(const float4*)&W_hh[(size_t)grow * HID + c4];
    }
    for (int i = tid; i < 48; i += 256) {
        int grow = (i >> 4) * HID + s * HS + (i & 15);
        bsm[i] = b_hh[grow];
    }

    const int tx = tid & 15, ty = tid >> 4;
    const float* wp0 = &Ws[(3 * tx + 0) * WPAD];
    const float* wp1 = wp0 + WPAD;
    const float* wp2 = wp0 + 2 * WPAD;
    const float* hp0 = &hs[(2 * ty) * WPAD];
    const float* hp1 = hp0 + WPAD;

    for (int t = 0; t < SEQ; t++) {
        grid_barrier(gridDim.x);
        const float* hsrc = (t & 1) ? g_hB : g_hA;
        float*       hdst = (t & 1) ? g_hA : g_hB;

        // load h tile (32 x 256)
        for (int i = tid; i < BT * (HID / 4); i += 256) {
            int r = i >> 6;
            int c4 = (i & 63) * 4;
            *(float4*)&hs[r * WPAD + c4] =
                *(const float4*)&hsrc[(size_t)(bt * BT + r) * HID + c4];
        }
        __syncthreads();

        // 2x3 register-tile GEMM: gh = h @ W_strip^T
        float a00 = 0.f, a01 = 0.f, a02 = 0.f, a10 = 0.f, a11 = 0.f, a12 = 0.f;
#pragma unroll 4
        for (int k = 0; k < HID; k += 4) {
            const float4 h0 = *(const float4*)(hp0 + k);
            const float4 h1 = *(const float4*)(hp1 + k);
            const float4 w0 = *(const float4*)(wp0 + k);
            const float4 w1 = *(const float4*)(wp1 + k);
            const float4 w2 = *(const float4*)(wp2 + k);
            a00 = fmaf(h0.x, w0.x, a00); a00 = fmaf(h0.y, w0.y, a00);
            a00 = fmaf(h0.z, w0.z, a00); a00 = fmaf(h0.w, w0.w, a00);
            a01 = fmaf(h0.x, w1.x, a01); a01 = fmaf(h0.y, w1.y, a01);
            a01 = fmaf(h0.z, w1.z, a01); a01 = fmaf(h0.w, w1.w, a01);
            a02 = fmaf(h0.x, w2.x, a02); a02 = fmaf(h0.y, w2.y, a02);
            a02 = fmaf(h0.z, w2.z, a02); a02 = fmaf(h0.w, w2.w, a02);
            a10 = fmaf(h1.x, w0.x, a10); a10 = fmaf(h1.y, w0.y, a10);
            a10 = fmaf(h1.z, w0.z, a10); a10 = fmaf(h1.w, w0.w, a10);
            a11 = fmaf(h1.x, w1.x, a11); a11 = fmaf(h1.y, w1.y, a11);
            a11 = fmaf(h1.z, w1.z, a11); a11 = fmaf(h1.w, w1.w, a11);
            a12 = fmaf(h1.x, w2.x, a12); a12 = fmaf(h1.y, w2.y, a12);
            a12 = fmaf(h1.z, w2.z, a12); a12 = fmaf(h1.w, w2.w, a12);
        }
        Gs[(2 * ty + 0) * 52 + 3 * tx + 0] = a00;
        Gs[(2 * ty + 0) * 52 + 3 * tx + 1] = a01;
        Gs[(2 * ty + 0) * 52 + 3 * tx + 2] = a02;
        Gs[(2 * ty + 1) * 52 + 3 * tx + 0] = a10;
        Gs[(2 * ty + 1) * 52 + 3 * tx + 1] = a11;
        Gs[(2 * ty + 1) * 52 + 3 * tx + 2] = a12;
        __syncthreads();

        // gate math + h update for the (32 x 16) tile.
        // BT*HS = 512 elements, 256 threads -> exactly 2 per thread (unrolled).
#pragma unroll
        for (int it = 0; it < 2; it++) {
            int e = tid + it * 256;
            int row = e >> 4, j = e & 15;
            float ghr = Gs[row * 52 + j]      + bsm[j];
            float ghz = Gs[row * 52 + 16 + j] + bsm[16 + j];
            float ghn = Gs[row * 52 + 32 + j] + bsm[32 + j];
            const float* gxp =
                &gx[((size_t)t * BATCH + bt * BT + row) * G3 + s * HS + j];
            float r_ = fast_sigmoid(gxp[0]   + ghr);
            float z_ = fast_sigmoid(gxp[256] + ghz);
            float n_ = fast_tanh(gxp[512] + r_ * ghn);
            float hprev = hs[row * WPAD + s * HS + j];
            float hnew = (1.f - z_) * n_ + z_ * hprev;
            hdst[(size_t)(bt * BT + row) * HID + s * HS + j] = hnew;
            if (STORE_ALL)
                h_all[((size_t)t * BATCH + bt * BT + row) * HID + s * HS + j] = hnew;
        }
        // next iteration's grid_barrier provides the inter-step sync
    }
}

// --------------------------------------------------------------------------
extern "C" void kernel_launch(void* const* d_in, const int* in_sizes, int n_in,
                              void* d_out, int out_size)
{
    const float* x     = (const float*)d_in[0];
    const float* W_ih0 = (const float*)d_in[1];
    const float* W_hh0 = (const float*)d_in[2];
    const float* b_ih0 = (const float*)d_in[3];
    const float* b_hh0 = (const float*)d_in[4];
    const float* W_ih1 = (const float*)d_in[5];
    const float* W_hh1 = (const float*)d_in[6];
    const float* b_ih1 = (const float*)d_in[7];
    const float* b_hh1 = (const float*)d_in[8];
    const float* fc_w  = (const float*)d_in[9];
    const float* fc_b  = (const float*)d_in[10];
    float* out = (float*)d_out;

    float *gx, *h0out, *hA;
    cudaGetSymbolAddress((void**)&gx, g_gx);
    cudaGetSymbolAddress((void**)&h0out, g_h0out);
    cudaGetSymbolAddress((void**)&hA, g_hA);

    const size_t scan_smem =
        (48 * WPAD + BT * WPAD + BT * 52 + 48) * sizeof(float); // ~90 KB
    cudaFuncSetAttribute(gru_scan_kernel<true>,
                         cudaFuncAttributeMaxDynamicSharedMemorySize, (int)scan_smem);
    cudaFuncSetAttribute(gru_scan_kernel<false>,
                         cudaFuncAttributeMaxDynamicSharedMemorySize, (int)scan_smem);

    const int M = SEQ * BATCH;

    // layer 0: gx = x @ W_ih0^T + b_ih0   (K = 58)
    {
        dim3 grid(G3 / 64, M / 64);
        gemm_bias_kernel<<<grid, 256>>>(x, W_ih0, b_ih0, gx, M, G3, INS);
    }
    zero_h_kernel<<<BATCH * HID / 256, 256>>>();
    gru_scan_kernel<true><<<SCAN_BLOCKS, 256, scan_smem>>>(W_hh0, b_hh0, gx, h0out);

    // layer 1: gx = h0out @ W_ih1^T + b_ih1   (K = 256)
    {
        dim3 grid(G3 / 64, M / 64);
        gemm_bias_kernel<<<grid, 256>>>(h0out, W_ih1, b_ih1, gx, M, G3, HID);
    }
    zero_h_kernel<<<BATCH * HID / 256, 256>>>();
    gru_scan_kernel<false><<<SCAN_BLOCKS, 256, scan_smem>>>(W_hh1, b_hh1, gx, nullptr);

    // final FC on last h (SEQ even -> final state lives in g_hA)
    {
        dim3 grid(1, BATCH / 64);
        gemm_bias_kernel<<<grid, 256>>>(hA, fc_w, fc_b, out, BATCH, NCAT, HID);
    }
}

// round 12
// speedup vs baseline: 1.3228x; 1.3228x over previous
#include <cuda_runtime.h>
#include <cstdint>
#include <math.h>

#define SEQ   512
#define BATCH 256
#define INS   58
#define HID   256
#define G3    768
#define NCAT  18

#define SCAN_BLOCKS 128
#define BT 32      // batch tile per block
#define HS 16      // hidden strip per block (gates = 3*HS = 48 rows of W_hh)
#define WPAD 260   // padded row stride for smem tiles (floats, /4 aligned)
#define NGROUPS 8  // independent barrier groups (one per batch tile)

// ---------------- device scratch (static allocation only) ----------------
__device__ float g_gx[(size_t)SEQ * BATCH * G3];     // reused per layer
__device__ float g_h0out[(size_t)SEQ * BATCH * HID]; // layer-0 outputs
__device__ float g_hA[BATCH * HID];
__device__ float g_hB[BATCH * HID];
__device__ unsigned g_bar_count[NGROUPS * 32];       // padded: 128B per group
__device__ unsigned g_bar_gen[NGROUPS * 32];

// ---------------- fast gate math -----------------------------------------
__device__ __forceinline__ float fast_sigmoid(float x) {
    return 1.0f / (1.0f + __expf(-x));
}
__device__ __forceinline__ float fast_tanh(float x) {
    return 1.0f - 2.0f / (__expf(2.0f * x) + 1.0f);
}

// ---------------- group barrier: nb co-resident blocks, padded slots -----
__device__ __forceinline__ void group_barrier(int g, unsigned nb) {
    __syncthreads();
    if (threadIdx.x == 0) {
        __threadfence();                       // release this block's writes
        volatile unsigned* genp = &g_bar_gen[g * 32];
        unsigned gen = *genp;
        if (atomicAdd(&g_bar_count[g * 32], 1u) == nb - 1u) {
            g_bar_count[g * 32] = 0u;
            __threadfence();
            *genp = gen + 1u;
        } else {
            while (*genp == gen) { }
        }
        __threadfence();                       // acquire peer writes
    }
    __syncthreads();
}

// ---------------- GEMM: C[M,N] = A[M,K] @ W[N,K]^T + bias[N] --------------
// 128x128 block tile, 8x8 microtile per thread (256 threads), 1 B/FMA smem.
__global__ __launch_bounds__(256) void gemm128_bias_kernel(
    const float* __restrict__ A, const float* __restrict__ W,
    const float* __restrict__ bias, float* __restrict__ C,
    int M, int N, int K)
{
    __shared__ float As[16][132];
    __shared__ float Bs[16][132];
    const int tid = threadIdx.x;
    const int tx = tid & 15, ty = tid >> 4;
    const int m0 = blockIdx.y * 128, n0 = blockIdx.x * 128;
    const int lr = tid >> 1;            // 0..127: row within tile
    const int lk = (tid & 1) * 8;       // k half: 0 or 8

    float acc[8][8];
#pragma unroll
    for (int i = 0; i < 8; i++)
#pragma unroll
        for (int j = 0; j < 8; j++) acc[i][j] = 0.f;

    for (int kk = 0; kk < K; kk += 16) {
        {
            int gm = m0 + lr;
#pragma unroll
            for (int j = 0; j < 8; j++) {
                int gk = kk + lk + j;
                float v = (gm < M && gk < K) ? A[(size_t)gm * K + gk] : 0.f;
                As[lk + j][lr] = v;
            }
            int gn = n0 + lr;
#pragma unroll
            for (int j = 0; j < 8; j++) {
                int gk = kk + lk + j;
                float v = (gn < N && gk < K) ? W[(size_t)gn * K + gk] : 0.f;
                Bs[lk + j][lr] = v;
            }
        }
        __syncthreads();
#pragma unroll
        for (int k = 0; k < 16; k++) {
            float a[8], b[8];
            *(float4*)&a[0] = *(const float4*)&As[k][ty * 8];
            *(float4*)&a[4] = *(const float4*)&As[k][ty * 8 + 4];
            *(float4*)&b[0] = *(const float4*)&Bs[k][tx * 8];
            *(float4*)&b[4] = *(const float4*)&Bs[k][tx * 8 + 4];
#pragma unroll
            for (int i = 0; i < 8; i++)
#pragma unroll
                for (int j = 0; j < 8; j++)
                    acc[i][j] = fmaf(a[i], b[j], acc[i][j]);
        }
        __syncthreads();
    }
#pragma unroll
    for (int i = 0; i < 8; i++) {
        int gm = m0 + ty * 8 + i;
        if (gm >= M) continue;
#pragma unroll
        for (int j = 0; j < 8; j++) {
            int gn = n0 + tx * 8 + j;
            if (gn < N) C[(size_t)gm * N + gn] = acc[i][j] + bias[gn];
        }
    }
}

// ---------------- zero the initial hidden state --------------------------
__global__ void zero_h_kernel() {
    g_hA[blockIdx.x * 256 + threadIdx.x] = 0.f;
}

// ---------------- persistent GRU scan over T ------------------------------
// 128 blocks = 8 batch-groups x 16 hidden strips. Blocks only exchange h
// within their group -> per-group 16-block barrier. gx prefetched at step top.
template <bool STORE_ALL>
__global__ __launch_bounds__(256) void gru_scan_kernel(
    const float* __restrict__ W_hh, const float* __restrict__ b_hh,
    const float* __restrict__ gx, float* __restrict__ h_all)
{
    extern __shared__ float sm[];
    float* Ws  = sm;                       // 48 * WPAD
    float* hs  = Ws + 48 * WPAD;           // BT * WPAD
    float* Gs  = hs + BT * WPAD;           // BT * 52
    float* bsm = Gs + BT * 52;             // 48

    const int tid = threadIdx.x;
    const int bt = blockIdx.x >> 4;        // 0..7   (batch tile / barrier group)
    const int s  = blockIdx.x & 15;        // 0..15  (hidden strip)

    // load persistent W_hh strip: local row lr -> global row (lr/16)*256 + s*16 + lr%16
    for (int i = tid; i < 48 * (HID / 4); i += 256) {
        int lr = i >> 6;
        int c4 = (i & 63) * 4;
        int grow = (lr >> 4) * HID + s * HS + (lr & 15);
        *(float4*)&Ws[lr * WPAD + c4] = *(const float4*)&W_hh[(size_t)grow * HID + c4];
    }
    for (int i = tid; i < 48; i += 256) {
        int grow = (i >> 4) * HID + s * HS + (i & 15);
        bsm[i] = b_hh[grow];
    }

    const int tx = tid & 15, ty = tid >> 4;
    const float* wp0 = &Ws[(3 * tx + 0) * WPAD];
    const float* wp1 = wp0 + WPAD;
    const float* wp2 = wp0 + 2 * WPAD;
    const float* hp0 = &hs[(2 * ty) * WPAD];
    const float* hp1 = hp0 + WPAD;

    // fixed per-thread gate coordinates (rows row0 and row0+16, column jj)
    const int row0 = tid >> 4, jj = tid & 15;
    const float* gxp0 = gx + (size_t)(bt * BT + row0) * G3 + s * HS + jj;
    const float* gxp1 = gxp0 + (size_t)16 * G3;
    const size_t hoff0 = (size_t)(bt * BT + row0) * HID + s * HS + jj;
    const size_t hoff1 = hoff0 + (size_t)16 * HID;

    for (int t = 0; t < SEQ; t++) {
        group_barrier(bt, 16);
        const float* hsrc = (t & 1) ? g_hB : g_hA;
        float*       hdst = (t & 1) ? g_hA : g_hB;

        // prefetch this step's gx gates (consumed after the FMA loop)
        const size_t gxo = (size_t)t * BATCH * G3;
        float pr0 = __ldg(gxp0 + gxo);
        float pz0 = __ldg(gxp0 + gxo + 256);
        float pn0 = __ldg(gxp0 + gxo + 512);
        float pr1 = __ldg(gxp1 + gxo);
        float pz1 = __ldg(gxp1 + gxo + 256);
        float pn1 = __ldg(gxp1 + gxo + 512);

        // load h tile (32 x 256)
        for (int i = tid; i < BT * (HID / 4); i += 256) {
            int r = i >> 6;
            int c4 = (i & 63) * 4;
            *(float4*)&hs[r * WPAD + c4] =
                *(const float4*)&hsrc[(size_t)(bt * BT + r) * HID + c4];
        }
        __syncthreads();

        // 2x3 register-tile GEMM: gh = h @ W_strip^T
        float a00 = 0.f, a01 = 0.f, a02 = 0.f, a10 = 0.f, a11 = 0.f, a12 = 0.f;
#pragma unroll 4
        for (int k = 0; k < HID; k += 4) {
            const float4 h0 = *(const float4*)(hp0 + k);
            const float4 h1 = *(const float4*)(hp1 + k);
            const float4 w0 = *(const float4*)(wp0 + k);
            const float4 w1 = *(const float4*)(wp1 + k);
            const float4 w2 = *(const float4*)(wp2 + k);
            a00 = fmaf(h0.x, w0.x, a00); a00 = fmaf(h0.y, w0.y, a00);
            a00 = fmaf(h0.z, w0.z, a00); a00 = fmaf(h0.w, w0.w, a00);
            a01 = fmaf(h0.x, w1.x, a01); a01 = fmaf(h0.y, w1.y, a01);
            a01 = fmaf(h0.z, w1.z, a01); a01 = fmaf(h0.w, w1.w, a01);
            a02 = fmaf(h0.x, w2.x, a02); a02 = fmaf(h0.y, w2.y, a02);
            a02 = fmaf(h0.z, w2.z, a02); a02 = fmaf(h0.w, w2.w, a02);
            a10 = fmaf(h1.x, w0.x, a10); a10 = fmaf(h1.y, w0.y, a10);
            a10 = fmaf(h1.z, w0.z, a10); a10 = fmaf(h1.w, w0.w, a10);
            a11 = fmaf(h1.x, w1.x, a11); a11 = fmaf(h1.y, w1.y, a11);
            a11 = fmaf(h1.z, w1.z, a11); a11 = fmaf(h1.w, w1.w, a11);
            a12 = fmaf(h1.x, w2.x, a12); a12 = fmaf(h1.y, w2.y, a12);
            a12 = fmaf(h1.z, w2.z, a12); a12 = fmaf(h1.w, w2.w, a12);
        }
        Gs[(2 * ty + 0) * 52 + 3 * tx + 0] = a00;
        Gs[(2 * ty + 0) * 52 + 3 * tx + 1] = a01;
        Gs[(2 * ty + 0) * 52 + 3 * tx + 2] = a02;
        Gs[(2 * ty + 1) * 52 + 3 * tx + 0] = a10;
        Gs[(2 * ty + 1) * 52 + 3 * tx + 1] = a11;
        Gs[(2 * ty + 1) * 52 + 3 * tx + 2] = a12;
        __syncthreads();

        // gate math + h update: rows row0 and row0+16, column jj (512 elems total)
        {
            float ghr = Gs[row0 * 52 + jj]      + bsm[jj];
            float ghz = Gs[row0 * 52 + 16 + jj] + bsm[16 + jj];
            float ghn = Gs[row0 * 52 + 32 + jj] + bsm[32 + jj];
            float r_ = fast_sigmoid(pr0 + ghr);
            float z_ = fast_sigmoid(pz0 + ghz);
            float n_ = fast_tanh(pn0 + r_ * ghn);
            float hprev = hs[row0 * WPAD + s * HS + jj];
            float hnew = (1.f - z_) * n_ + z_ * hprev;
            hdst[hoff0] = hnew;
            if (STORE_ALL) h_all[(size_t)t * BATCH * HID + hoff0] = hnew;
        }
        {
            int row1 = row0 + 16;
            float ghr = Gs[row1 * 52 + jj]      + bsm[jj];
            float ghz = Gs[row1 * 52 + 16 + jj] + bsm[16 + jj];
            float ghn = Gs[row1 * 52 + 32 + jj] + bsm[32 + jj];
            float r_ = fast_sigmoid(pr1 + ghr);
            float z_ = fast_sigmoid(pz1 + ghz);
            float n_ = fast_tanh(pn1 + r_ * ghn);
            float hprev = hs[row1 * WPAD + s * HS + jj];
            float hnew = (1.f - z_) * n_ + z_ * hprev;
            hdst[hoff1] = hnew;
            if (STORE_ALL) h_all[(size_t)t * BATCH * HID + hoff1] = hnew;
        }
    }
}

// --------------------------------------------------------------------------
extern "C" void kernel_launch(void* const* d_in, const int* in_sizes, int n_in,
                              void* d_out, int out_size)
{
    const float* x     = (const float*)d_in[0];
    const float* W_ih0 = (const float*)d_in[1];
    const float* W_hh0 = (const float*)d_in[2];
    const float* b_ih0 = (const float*)d_in[3];
    const float* b_hh0 = (const float*)d_in[4];
    const float* W_ih1 = (const float*)d_in[5];
    const float* W_hh1 = (const float*)d_in[6];
    const float* b_ih1 = (const float*)d_in[7];
    const float* b_hh1 = (const float*)d_in[8];
    const float* fc_w  = (const float*)d_in[9];
    const float* fc_b  = (const float*)d_in[10];
    float* out = (float*)d_out;

    float *gx, *h0out, *hA;
    cudaGetSymbolAddress((void**)&gx, g_gx);
    cudaGetSymbolAddress((void**)&h0out, g_h0out);
    cudaGetSymbolAddress((void**)&hA, g_hA);

    const size_t scan_smem =
        (48 * WPAD + BT * WPAD + BT * 52 + 48) * sizeof(float); // ~90 KB
    cudaFuncSetAttribute(gru_scan_kernel<true>,
                         cudaFuncAttributeMaxDynamicSharedMemorySize, (int)scan_smem);
    cudaFuncSetAttribute(gru_scan_kernel<false>,
                         cudaFuncAttributeMaxDynamicSharedMemorySize, (int)scan_smem);

    const int M = SEQ * BATCH;

    // layer 0: gx = x @ W_ih0^T + b_ih0   (K = 58)
    {
        dim3 grid(G3 / 128, M / 128);
        gemm128_bias_kernel<<<grid, 256>>>(x, W_ih0, b_ih0, gx, M, G3, INS);
    }
    zero_h_kernel<<<BATCH * HID / 256, 256>>>();
    gru_scan_kernel<true><<<SCAN_BLOCKS, 256, scan_smem>>>(W_hh0, b_hh0, gx, h0out);

    // layer 1: gx = h0out @ W_ih1^T + b_ih1   (K = 256)
    {
        dim3 grid(G3 / 128, M / 128);
        gemm128_bias_kernel<<<grid, 256>>>(h0out, W_ih1, b_ih1, gx, M, G3, HID);
    }
    zero_h_kernel<<<BATCH * HID / 256, 256>>>();
    gru_scan_kernel<false><<<SCAN_BLOCKS, 256, scan_smem>>>(W_hh1, b_hh1, gx, nullptr);

    // final FC on last h (SEQ even -> final state lives in g_hA)
    {
        dim3 grid(1, (BATCH + 127) / 128);
        gemm128_bias_kernel<<<grid, 256>>>(hA, fc_w, fc_b, out, BATCH, NCAT, HID);
    }
}